// round 14
// baseline (speedup 1.0000x reference)
#include <cuda_runtime.h>
#include <cuda_fp16.h>
#include <cstdint>

// ---------------- problem constants ----------------
#define BATCH 4
#define SEQ   4096
#define QD    1024
#define HEADS 8
#define DH    64
#define HID   512
#define MROWS (BATCH*SEQ)     // 16384
#define NTOT  1536            // q|k|v packed columns
#define QSCALE 0.125f
#define NCH   64              // n-chunks for k stats
#define CHROWS (SEQ/NCH)      // 64
#define CCH   16              // n-chunks for context
#define CCROWS (SEQ/CCH)      // 256

// ---------------- scratch layout (bytes) ----------------
#define SC_XH     0ull                   // x fp16 [16384][1024]
#define SC_WTH    33554432ull            // W^T fp16 [1536][1024]
#define SC_QH     36700160ull            // q_soft fp16 [16384][512]
#define SC_KH     53477376ull            // k fp16 [16384][512]
#define SC_VH     70254592ull            // v fp16 [16384][512]
#define SC_KSI    87031808ull            // [4][512] fp32
#define SC_CTXP   87040000ull            // [16][4][8][64][64] fp32 = 8388608 B
#define SC_W2TH   95428608ull            // W2^T fp16 [4][1024][512]
#define SC_PSUM   99622912ull            // [4][64][512] fp32
#define SC_TOTAL  100147200ull

__device__ __align__(1024) unsigned char g_scratch[SC_TOTAL];

// ---------------- PTX helpers ----------------
__device__ __forceinline__ uint32_t smem_u32(const void* p) {
    uint32_t a;
    asm("{ .reg .u64 t; cvta.to.shared.u64 t, %1; cvt.u32.u64 %0, t; }" : "=r"(a) : "l"(p));
    return a;
}
__device__ __forceinline__ void cp_async16(uint32_t dst, const void* src) {
    asm volatile("cp.async.cg.shared.global [%0], [%1], 16;" :: "r"(dst), "l"(src) : "memory");
}
__device__ __forceinline__ void cp_commit() {
    asm volatile("cp.async.commit_group;" ::: "memory");
}
__device__ __forceinline__ void ldsm_x4(uint32_t& r0, uint32_t& r1, uint32_t& r2, uint32_t& r3,
                                        uint32_t addr) {
    asm volatile("ldmatrix.sync.aligned.m8n8.x4.shared.b16 {%0,%1,%2,%3}, [%4];"
                 : "=r"(r0), "=r"(r1), "=r"(r2), "=r"(r3) : "r"(addr));
}
__device__ __forceinline__ void mma_f16(float* d, const uint32_t* a, const uint32_t* b) {
    asm volatile(
        "mma.sync.aligned.m16n8k16.row.col.f32.f16.f16.f32 "
        "{%0,%1,%2,%3}, {%4,%5,%6,%7}, {%8,%9}, {%0,%1,%2,%3};"
        : "+f"(d[0]), "+f"(d[1]), "+f"(d[2]), "+f"(d[3])
        : "r"(a[0]), "r"(a[1]), "r"(a[2]), "r"(a[3]), "r"(b[0]), "r"(b[1]));
}

// smem stage: A 16KB | B 32KB = 48KB per stage, 3 stages = 144KB
#define STG_B  16384
#define STG_SZ 49152
#define GSM_TOTAL (3*STG_SZ)   // 147456

// ---------------------------------------------------------------------------
// pure fp16 GEMM via mma.sync: C = A @ B^T.  (R10/R12 formulation — frozen)
// CTA tile 128(M) x 256(N), BK=64, 256 threads (8 warps 2x4; warp = 64x64).
// fuse=0: fp32 out + bias. fuse=1: QKV softmax/convert epilogue.
// grid: (N/256, M/128, batch)
// ---------------------------------------------------------------------------
__global__ __launch_bounds__(256, 1)
void gemm_mma(const __half* __restrict__ A, const __half* __restrict__ B,
              float* __restrict__ C, const float* __restrict__ bias,
              __half* __restrict__ qh, __half* __restrict__ kh, __half* __restrict__ vh,
              int fuse, int K, int ldc,
              long long sA, long long sB, long long sC)
{
    extern __shared__ char smem[];
    const uint32_t sb = smem_u32(smem);
    const int tid  = threadIdx.x;
    const int wid  = tid >> 5;
    const int lane = tid & 31;
    const int wm = wid >> 2;           // 0..1
    const int wn = wid & 3;            // 0..3

    const int n0 = blockIdx.x * 256;
    const int m0 = blockIdx.y * 128;
    const long long bz = blockIdx.z;
    const __half* aP = A + bz * sA + (size_t)m0 * K;
    const __half* bP = B + bz * sB + (size_t)n0 * K;

    const int NC = K >> 6;

    float acc[4][8][4];
    #pragma unroll
    for (int i = 0; i < 4; i++)
        #pragma unroll
        for (int j = 0; j < 8; j++)
            #pragma unroll
            for (int l = 0; l < 4; l++) acc[i][j][l] = 0.f;

    const int g  = lane >> 3;     // ldmatrix address group 0..3
    const int lr = lane & 7;

#define ISSUE(cc, ss) do {                                                       \
    const int ck_ = (cc) << 6;                                                   \
    const uint32_t bs_ = sb + (ss) * STG_SZ;                                     \
    _Pragma("unroll")                                                            \
    for (int j_ = 0; j_ < 4; j_++) {                                             \
        int idx_ = tid + j_ * 256;                                               \
        int r_ = idx_ >> 3, c16_ = idx_ & 7;                                     \
        uint32_t d_ = bs_ + (uint32_t)(r_ * 128 + ((c16_ ^ (r_ & 7)) << 4));     \
        cp_async16(d_, aP + (size_t)r_ * K + ck_ + c16_ * 8);                    \
    }                                                                            \
    _Pragma("unroll")                                                            \
    for (int j_ = 0; j_ < 8; j_++) {                                             \
        int idx_ = tid + j_ * 256;                                               \
        int r_ = idx_ >> 3, c16_ = idx_ & 7;                                     \
        uint32_t d_ = bs_ + STG_B + (uint32_t)(r_ * 128 + ((c16_ ^ (r_ & 7)) << 4)); \
        cp_async16(d_, bP + (size_t)r_ * K + ck_ + c16_ * 8);                    \
    }                                                                            \
    cp_commit();                                                                 \
} while (0)

#define COMPUTE(ss) do {                                                         \
    const uint32_t bs_ = sb + (ss) * STG_SZ;                                     \
    _Pragma("unroll")                                                            \
    for (int ks = 0; ks < 4; ks++) {                                             \
        uint32_t ah[4][4];                                                       \
        _Pragma("unroll")                                                        \
        for (int mt = 0; mt < 4; mt++) {                                         \
            int r_ = wm * 64 + mt * 16 + lr + (g & 1) * 8;                       \
            int cA_ = ks * 2 + (g >> 1);                                         \
            uint32_t ad_ = bs_ + (uint32_t)(r_ * 128 + ((cA_ ^ (r_ & 7)) << 4)); \
            ldsm_x4(ah[mt][0], ah[mt][1], ah[mt][2], ah[mt][3], ad_);            \
        }                                                                        \
        _Pragma("unroll")                                                        \
        for (int np = 0; np < 4; np++) {                                         \
            int n_ = wn * 64 + np * 16 + lr + (g >> 1) * 8;                      \
            int cB_ = ks * 2 + (g & 1);                                          \
            uint32_t bd_ = bs_ + STG_B +                                         \
                           (uint32_t)(n_ * 128 + ((cB_ ^ (n_ & 7)) << 4));       \
            uint32_t b0[2], b1[2], t0, t1, t2, t3;                               \
            ldsm_x4(t0, t1, t2, t3, bd_);                                        \
            b0[0] = t0; b0[1] = t1; b1[0] = t2; b1[1] = t3;                      \
            _Pragma("unroll")                                                    \
            for (int mt = 0; mt < 4; mt++) {                                     \
                mma_f16(acc[mt][np * 2],     ah[mt], b0);                        \
                mma_f16(acc[mt][np * 2 + 1], ah[mt], b1);                        \
            }                                                                    \
        }                                                                        \
    }                                                                            \
} while (0)

    ISSUE(0, 0);
    ISSUE(1, 1);
    for (int c = 0; c < NC; ++c) {
        if (c + 2 < NC) {
            ISSUE(c + 2, (c + 2) % 3);
            asm volatile("cp.async.wait_group 2;" ::: "memory");
        } else if (c + 1 < NC) {
            asm volatile("cp.async.wait_group 1;" ::: "memory");
        } else {
            asm volatile("cp.async.wait_group 0;" ::: "memory");
        }
        __syncthreads();
        COMPUTE(c % 3);
        __syncthreads();
    }

    if (!fuse) {
        float* Cb = C + bz * sC;
        const int rbase = m0 + wm * 64 + (lane >> 2);
        const int cbase = n0 + wn * 64 + (lane & 3) * 2;
        #pragma unroll
        for (int mt = 0; mt < 4; mt++) {
            #pragma unroll
            for (int nt = 0; nt < 8; nt++) {
                int row = rbase + mt * 16;
                int col = cbase + nt * 8;
                float bx = bias[col], by = bias[col + 1];
                float2 v0 = make_float2(acc[mt][nt][0] + bx, acc[mt][nt][1] + by);
                float2 v1 = make_float2(acc[mt][nt][2] + bx, acc[mt][nt][3] + by);
                *(float2*)(Cb + (size_t)row * ldc + col)       = v0;
                *(float2*)(Cb + (size_t)(row + 8) * ldc + col) = v1;
            }
        }
    } else {
        const int gcol = n0 + wn * 64;
        const int lsub = (lane & 3) * 2;
        #pragma unroll
        for (int mt = 0; mt < 4; mt++) {
            #pragma unroll
            for (int hf = 0; hf < 2; hf++) {
                const int row = m0 + wm * 64 + (lane >> 2) + mt * 16 + hf * 8;
                float v[16];
                #pragma unroll
                for (int nt = 0; nt < 8; nt++) {
                    v[nt * 2]     = acc[mt][nt][hf * 2];
                    v[nt * 2 + 1] = acc[mt][nt][hf * 2 + 1];
                }
                if (gcol < 512) {
                    float m = v[0];
                    #pragma unroll
                    for (int i = 1; i < 16; i++) m = fmaxf(m, v[i]);
                    m = fmaxf(m, __shfl_xor_sync(0xffffffffu, m, 1));
                    m = fmaxf(m, __shfl_xor_sync(0xffffffffu, m, 2));
                    float s = 0.f;
                    #pragma unroll
                    for (int i = 0; i < 16; i++) { v[i] = __expf(v[i] - m); s += v[i]; }
                    s += __shfl_xor_sync(0xffffffffu, s, 1);
                    s += __shfl_xor_sync(0xffffffffu, s, 2);
                    const float sc = QSCALE / s;
                    #pragma unroll
                    for (int nt = 0; nt < 8; nt++) {
                        __half2 p = __floats2half2_rn(v[nt * 2] * sc, v[nt * 2 + 1] * sc);
                        *(__half2*)(qh + (size_t)row * HID + gcol + lsub + nt * 8) = p;
                    }
                } else {
                    __half* dst = (gcol < 1024) ? kh : vh;
                    const int cb2 = gcol - ((gcol < 1024) ? 512 : 1024);
                    #pragma unroll
                    for (int nt = 0; nt < 8; nt++) {
                        __half2 p = __floats2half2_rn(v[nt * 2], v[nt * 2 + 1]);
                        *(__half2*)(dst + (size_t)row * HID + cb2 + lsub + nt * 8) = p;
                    }
                }
            }
        }
    }
#undef ISSUE
#undef COMPUTE
}

// ---------------------------------------------------------------------------
// x fp32 -> fp16
// ---------------------------------------------------------------------------
__global__ void cvt_x_kernel(const float4* __restrict__ x, uint2* __restrict__ xh)
{
    size_t i = (size_t)blockIdx.x * 256 + threadIdx.x;
    float4 v = x[i];
    uint2 hv;
    __half2 p0 = __floats2half2_rn(v.x, v.y);
    __half2 p1 = __floats2half2_rn(v.z, v.w);
    hv.x = *(uint32_t*)&p0;
    hv.y = *(uint32_t*)&p1;
    xh[i] = hv;
}

// ---------------------------------------------------------------------------
// pack Wq|Wk|Wv [1024][512] -> W^T fp16 [1536][1024]
// ---------------------------------------------------------------------------
__global__ void pack_w_kernel(const float* __restrict__ Wq, const float* __restrict__ Wk,
                              const float* __restrict__ Wv, __half* __restrict__ wth)
{
    __shared__ float t[32][33];
    const float* W = (blockIdx.z == 0) ? Wq : (blockIdx.z == 1) ? Wk : Wv;
    int k = blockIdx.x * 32 + threadIdx.y;
    int c = blockIdx.y * 32 + threadIdx.x;
    t[threadIdx.y][threadIdx.x] = W[(size_t)k * 512 + c];
    __syncthreads();
    int n  = blockIdx.z * 512 + blockIdx.y * 32 + threadIdx.y;
    int kk = blockIdx.x * 32 + threadIdx.x;
    wth[(size_t)n * 1024 + kk] = __float2half_rn(t[threadIdx.x][threadIdx.y]);
}

// ---------------------------------------------------------------------------
// k stats phase 1 (single pass, no max shift): per-(b, chunk, c) sum(exp(k)).
// grid (HID/128, NCH, BATCH), block 128.
// ---------------------------------------------------------------------------
__global__ void k_stats_part(const __half* __restrict__ kh, float* __restrict__ psum)
{
    const int b  = blockIdx.z;
    const int ch = blockIdx.y;
    const int c  = blockIdx.x * 128 + threadIdx.x;
    const __half* base = kh + (size_t)b * SEQ * HID + (size_t)ch * CHROWS * HID + c;

    float s = 0.f;
    #pragma unroll 8
    for (int n = 0; n < CHROWS; n++)
        s += __expf(__half2float(base[(size_t)n * HID]));

    psum[((size_t)b * NCH + ch) * HID + c] = s;
}

// ---------------------------------------------------------------------------
// k stats phase 2 (parallel combine): grid (HID/16, BATCH), block (16,16).
// Each thread sums 4 of 64 chunk partials; 16-way smem reduce per column.
// ---------------------------------------------------------------------------
__global__ void k_stats_final(const float* __restrict__ psum, float* __restrict__ ksi)
{
    const int b  = blockIdx.y;
    const int c  = blockIdx.x * 16 + threadIdx.x;
    const int ty = threadIdx.y;

    __shared__ float red[16][17];

    float s = 0.f;
    #pragma unroll
    for (int j = 0; j < 4; j++)
        s += psum[((size_t)b * NCH + ty * 4 + j) * HID + c];
    red[ty][threadIdx.x] = s;
    __syncthreads();

    if (ty == 0) {
        float t = 0.f;
        #pragma unroll
        for (int i = 0; i < 16; i++) t += red[i][threadIdx.x];
        ksi[b * HID + c] = 1.0f / t;
    }
}

// ---------------------------------------------------------------------------
// partial context over 256-token chunks from fp16 k/v buffers [16384][512]
// softk = exp(k) * ksi  (no max shift). grid (CCH, HEADS, BATCH).
// ---------------------------------------------------------------------------
__global__ __launch_bounds__(256, 4)
void context_kernel(const __half* __restrict__ kh, const __half* __restrict__ vh,
                    const float* __restrict__ ksi, float* __restrict__ ctxp)
{
    int chunk = blockIdx.x, h = blockIdx.y, b = blockIdx.z;
    int tx = threadIdx.x, ty = threadIdx.y;
    int tid = ty * 16 + tx;

    __shared__ float Ks[32][64];
    __shared__ float Vs[32][64];
    __shared__ float si[64];

    if (tid < 64) si[tid] = ksi[b * HID + h * DH + tid];
    __syncthreads();

    const __half* kb = kh + (size_t)b * SEQ * HID + h * DH;
    const __half* vb = vh + (size_t)b * SEQ * HID + h * DH;
    int n0 = chunk * CCROWS;

    float acc[4][4];
    #pragma unroll
    for (int r = 0; r < 4; r++)
        #pragma unroll
        for (int c = 0; c < 4; c++) acc[r][c] = 0.f;

    for (int nn = 0; nn < CCROWS; nn += 32) {
        int ii = tid >> 3;
        int d0 = (tid & 7) * 8;
        size_t off = (size_t)(n0 + nn + ii) * HID + d0;
        uint4 kv4 = *(const uint4*)(kb + off);
        uint4 vv4 = *(const uint4*)(vb + off);
        const __half2* kp = (const __half2*)&kv4;
        const __half2* vp = (const __half2*)&vv4;
        #pragma unroll
        for (int u = 0; u < 4; u++) {
            float2 kf = __half22float2(kp[u]);
            float2 vf = __half22float2(vp[u]);
            Ks[ii][d0 + u * 2 + 0] = __expf(kf.x) * si[d0 + u * 2 + 0];
            Ks[ii][d0 + u * 2 + 1] = __expf(kf.y) * si[d0 + u * 2 + 1];
            Vs[ii][d0 + u * 2 + 0] = vf.x;
            Vs[ii][d0 + u * 2 + 1] = vf.y;
        }
        __syncthreads();

        #pragma unroll
        for (int i = 0; i < 32; i++) {
            float4 rav = *(float4*)(&Ks[i][ty * 4]);
            float4 rbv = *(float4*)(&Vs[i][tx * 4]);
            float ra[4] = {rav.x, rav.y, rav.z, rav.w};
            float rb[4] = {rbv.x, rbv.y, rbv.z, rbv.w};
            #pragma unroll
            for (int r = 0; r < 4; r++)
                #pragma unroll
                for (int c = 0; c < 4; c++)
                    acc[r][c] += ra[r] * rb[c];
        }
        __syncthreads();
    }

    float* dst = ctxp + ((((size_t)chunk * BATCH + b) * HEADS + h) * DH) * DH;
    #pragma unroll
    for (int r = 0; r < 4; r++)
        #pragma unroll
        for (int c = 0; c < 4; c++)
            dst[(ty * 4 + r) * DH + tx * 4 + c] = acc[r][c];
}

// ---------------------------------------------------------------------------
// W2^T[b][j][k] = sum_e ctx[b][h][d][e]*Wo[h*64+e][j]  (k = h*64+d), fp16 out
// ---------------------------------------------------------------------------
__global__ void w2t_kernel(const float* __restrict__ ctxp, const float* __restrict__ Wo,
                           __half* __restrict__ w2th)
{
    int jt = blockIdx.x, h = blockIdx.y, b = blockIdx.z;
    int tx = threadIdx.x, ty = threadIdx.y;
    int tid = ty * 16 + tx;

    __shared__ float Cs[64][65];   // [d][e]
    __shared__ float Ws[64][64];   // [e][j]

    for (int l = tid; l < 4096; l += 256) {
        size_t base = ((size_t)b * HEADS + h) * 4096 + l;
        float s = 0.f;
        #pragma unroll
        for (int ch = 0; ch < CCH; ch++)
            s += ctxp[base + (size_t)ch * (BATCH * HEADS * 4096)];
        Cs[l >> 6][l & 63] = s;
    }
    for (int l = tid; l < 4096; l += 256) {
        int e = l >> 6, jj = l & 63;
        Ws[e][jj] = Wo[(size_t)(h * DH + e) * QD + jt * 64 + jj];
    }
    __syncthreads();

    float acc[4][4];
    #pragma unroll
    for (int a = 0; a < 4; a++)
        #pragma unroll
        for (int d = 0; d < 4; d++) acc[a][d] = 0.f;

    #pragma unroll
    for (int e = 0; e < 64; e++) {
        float wv[4], cv[4];
        #pragma unroll
        for (int a = 0; a < 4; a++) wv[a] = Ws[e][ty * 4 + a];
        #pragma unroll
        for (int d = 0; d < 4; d++) cv[d] = Cs[tx * 4 + d][e];
        #pragma unroll
        for (int a = 0; a < 4; a++)
            #pragma unroll
            for (int d = 0; d < 4; d++)
                acc[a][d] += wv[a] * cv[d];
    }

    #pragma unroll
    for (int a = 0; a < 4; a++) {
        int j = jt * 64 + ty * 4 + a;
        #pragma unroll
        for (int d = 0; d < 4; d++) {
            int kc = h * DH + tx * 4 + d;
            w2th[((size_t)b * QD + j) * HID + kc] = __float2half_rn(acc[a][d]);
        }
    }
}

// ---------------------------------------------------------------------------
extern "C" void kernel_launch(void* const* d_in, const int* in_sizes, int n_in,
                              void* d_out, int out_size)
{
    const float* x  = (const float*)d_in[0];
    const float* Wq = (const float*)d_in[1];
    const float* Wk = (const float*)d_in[2];
    const float* Wv = (const float*)d_in[3];
    const float* Wo = (const float*)d_in[4];
    const float* bo = (const float*)d_in[5];
    float* out = (float*)d_out;

    unsigned char* sc = nullptr;
    cudaGetSymbolAddress((void**)&sc, g_scratch);

    __half*  xh   = (__half*) (sc + SC_XH);
    __half*  wth  = (__half*) (sc + SC_WTH);
    __half*  qh   = (__half*) (sc + SC_QH);
    __half*  kh   = (__half*) (sc + SC_KH);
    __half*  vh   = (__half*) (sc + SC_VH);
    float*   ksi  = (float*)  (sc + SC_KSI);
    float*   ctxp = (float*)  (sc + SC_CTXP);
    __half*  w2h  = (__half*) (sc + SC_W2TH);
    float*   psum = (float*)  (sc + SC_PSUM);

    cudaFuncSetAttribute(gemm_mma, cudaFuncAttributeMaxDynamicSharedMemorySize, GSM_TOTAL);

    // 1) conversions
    cvt_x_kernel<<<MROWS * QD / (256 * 4), 256>>>((const float4*)x, (uint2*)xh);
    pack_w_kernel<<<dim3(32, 16, 3), dim3(32, 32)>>>(Wq, Wk, Wv, wth);

    // 2) QKV fused GEMM + fused softmax/convert epilogue
    gemm_mma<<<dim3(NTOT / 256, MROWS / 128, 1), 256, GSM_TOTAL>>>(
        xh, wth, nullptr, nullptr, qh, kh, vh, 1, QD, 0, 0, 0, 0);

    // 3) k stats (single-pass exp-sum, chunked 2-phase; final now parallel)
    k_stats_part <<<dim3(HID / 128, NCH, BATCH), 128>>>(kh, psum);
    k_stats_final<<<dim3(HID / 16, BATCH), dim3(16, 16)>>>(psum, ksi);

    // 4) partial context (16 chunks of 256 tokens)
    context_kernel<<<dim3(CCH, HEADS, BATCH), dim3(16, 16)>>>(kh, vh, ksi, ctxp);

    // 5) W2^T build (fp16)
    w2t_kernel<<<dim3(16, HEADS, BATCH), dim3(16, 16)>>>(ctxp, Wo, w2h);

    // 6) final batched GEMM: out[b] = q_soft[b] @ W2[b] + bo
    gemm_mma<<<dim3(QD / 256, SEQ / 128, BATCH), 256, GSM_TOTAL>>>(
        qh, w2h, out, bo, nullptr, nullptr, nullptr, 0, HID, QD,
        (long long)SEQ * HID, (long long)QD * HID, (long long)SEQ * QD);
}

// round 15
// speedup vs baseline: 1.4930x; 1.4930x over previous
#include <cuda_runtime.h>
#include <cuda_fp16.h>
#include <cstdint>

// ---------------- problem constants ----------------
#define BATCH 4
#define SEQ   4096
#define QD    1024
#define HEADS 8
#define DH    64
#define HID   512
#define MROWS (BATCH*SEQ)     // 16384
#define NTOT  1536            // q|k|v packed columns
#define QSCALE 0.125f
#define NCH   64              // n-chunks for k stats
#define CHROWS (SEQ/NCH)      // 64
#define CCH   16              // n-chunks for context
#define CCROWS (SEQ/CCH)      // 256

// ---------------- scratch layout (bytes) ----------------
#define SC_XH     0ull                   // x fp16 [16384][1024]
#define SC_WTH    33554432ull            // W^T fp16 [1536][1024]
#define SC_QH     36700160ull            // q_soft fp16 [16384][512]
#define SC_KH     53477376ull            // k fp16 [16384][512]
#define SC_VH     70254592ull            // v fp16 [16384][512]
#define SC_KSI    87031808ull            // [4][512] fp32
#define SC_CTXP   87040000ull            // [16][4][8][64][64] fp32 = 8388608 B
#define SC_W2TH   95428608ull            // W2^T fp16 [4][1024][512]
#define SC_PSUM   99622912ull            // [4][64][512] fp32
#define SC_TOTAL  100147200ull

__device__ __align__(1024) unsigned char g_scratch[SC_TOTAL];

// ---------------- PTX helpers ----------------
__device__ __forceinline__ uint32_t smem_u32(const void* p) {
    uint32_t a;
    asm("{ .reg .u64 t; cvta.to.shared.u64 t, %1; cvt.u32.u64 %0, t; }" : "=r"(a) : "l"(p));
    return a;
}
__device__ __forceinline__ void cp_async16(uint32_t dst, const void* src) {
    asm volatile("cp.async.cg.shared.global [%0], [%1], 16;" :: "r"(dst), "l"(src) : "memory");
}
__device__ __forceinline__ void cp_commit() {
    asm volatile("cp.async.commit_group;" ::: "memory");
}
__device__ __forceinline__ void ldsm_x4(uint32_t& r0, uint32_t& r1, uint32_t& r2, uint32_t& r3,
                                        uint32_t addr) {
    asm volatile("ldmatrix.sync.aligned.m8n8.x4.shared.b16 {%0,%1,%2,%3}, [%4];"
                 : "=r"(r0), "=r"(r1), "=r"(r2), "=r"(r3) : "r"(addr));
}
__device__ __forceinline__ void mma_f16(float* d, const uint32_t* a, const uint32_t* b) {
    asm volatile(
        "mma.sync.aligned.m16n8k16.row.col.f32.f16.f16.f32 "
        "{%0,%1,%2,%3}, {%4,%5,%6,%7}, {%8,%9}, {%0,%1,%2,%3};"
        : "+f"(d[0]), "+f"(d[1]), "+f"(d[2]), "+f"(d[3])
        : "r"(a[0]), "r"(a[1]), "r"(a[2]), "r"(a[3]), "r"(b[0]), "r"(b[1]));
}

// smem stage: A 16KB | B 32KB = 48KB per stage, 3 stages = 144KB
#define STG_B  16384
#define STG_SZ 49152
#define GSM_TOTAL (3*STG_SZ)   // 147456

// ---------------------------------------------------------------------------
// pure fp16 GEMM via mma.sync: C = A @ B^T.  (R10 formulation — frozen)
// CTA tile 128(M) x 256(N), BK=64, 256 threads (8 warps 2x4; warp = 64x64).
// fuse=0: fp32 out + bias. fuse=1: QKV softmax/convert epilogue.
// grid: (N/256, M/128, batch)
// ---------------------------------------------------------------------------
__global__ __launch_bounds__(256, 1)
void gemm_mma(const __half* __restrict__ A, const __half* __restrict__ B,
              float* __restrict__ C, const float* __restrict__ bias,
              __half* __restrict__ qh, __half* __restrict__ kh, __half* __restrict__ vh,
              int fuse, int K, int ldc,
              long long sA, long long sB, long long sC)
{
    extern __shared__ char smem[];
    const uint32_t sb = smem_u32(smem);
    const int tid  = threadIdx.x;
    const int wid  = tid >> 5;
    const int lane = tid & 31;
    const int wm = wid >> 2;           // 0..1
    const int wn = wid & 3;            // 0..3

    const int n0 = blockIdx.x * 256;
    const int m0 = blockIdx.y * 128;
    const long long bz = blockIdx.z;
    const __half* aP = A + bz * sA + (size_t)m0 * K;
    const __half* bP = B + bz * sB + (size_t)n0 * K;

    const int NC = K >> 6;

    float acc[4][8][4];
    #pragma unroll
    for (int i = 0; i < 4; i++)
        #pragma unroll
        for (int j = 0; j < 8; j++)
            #pragma unroll
            for (int l = 0; l < 4; l++) acc[i][j][l] = 0.f;

    const int g  = lane >> 3;     // ldmatrix address group 0..3
    const int lr = lane & 7;

#define ISSUE(cc, ss) do {                                                       \
    const int ck_ = (cc) << 6;                                                   \
    const uint32_t bs_ = sb + (ss) * STG_SZ;                                     \
    _Pragma("unroll")                                                            \
    for (int j_ = 0; j_ < 4; j_++) {                                             \
        int idx_ = tid + j_ * 256;                                               \
        int r_ = idx_ >> 3, c16_ = idx_ & 7;                                     \
        uint32_t d_ = bs_ + (uint32_t)(r_ * 128 + ((c16_ ^ (r_ & 7)) << 4));     \
        cp_async16(d_, aP + (size_t)r_ * K + ck_ + c16_ * 8);                    \
    }                                                                            \
    _Pragma("unroll")                                                            \
    for (int j_ = 0; j_ < 8; j_++) {                                             \
        int idx_ = tid + j_ * 256;                                               \
        int r_ = idx_ >> 3, c16_ = idx_ & 7;                                     \
        uint32_t d_ = bs_ + STG_B + (uint32_t)(r_ * 128 + ((c16_ ^ (r_ & 7)) << 4)); \
        cp_async16(d_, bP + (size_t)r_ * K + ck_ + c16_ * 8);                    \
    }                                                                            \
    cp_commit();                                                                 \
} while (0)

#define COMPUTE(ss) do {                                                         \
    const uint32_t bs_ = sb + (ss) * STG_SZ;                                     \
    _Pragma("unroll")                                                            \
    for (int ks = 0; ks < 4; ks++) {                                             \
        uint32_t ah[4][4];                                                       \
        _Pragma("unroll")                                                        \
        for (int mt = 0; mt < 4; mt++) {                                         \
            int r_ = wm * 64 + mt * 16 + lr + (g & 1) * 8;                       \
            int cA_ = ks * 2 + (g >> 1);                                         \
            uint32_t ad_ = bs_ + (uint32_t)(r_ * 128 + ((cA_ ^ (r_ & 7)) << 4)); \
            ldsm_x4(ah[mt][0], ah[mt][1], ah[mt][2], ah[mt][3], ad_);            \
        }                                                                        \
        _Pragma("unroll")                                                        \
        for (int np = 0; np < 4; np++) {                                         \
            int n_ = wn * 64 + np * 16 + lr + (g >> 1) * 8;                      \
            int cB_ = ks * 2 + (g & 1);                                          \
            uint32_t bd_ = bs_ + STG_B +                                         \
                           (uint32_t)(n_ * 128 + ((cB_ ^ (n_ & 7)) << 4));       \
            uint32_t b0[2], b1[2], t0, t1, t2, t3;                               \
            ldsm_x4(t0, t1, t2, t3, bd_);                                        \
            b0[0] = t0; b0[1] = t1; b1[0] = t2; b1[1] = t3;                      \
            _Pragma("unroll")                                                    \
            for (int mt = 0; mt < 4; mt++) {                                     \
                mma_f16(acc[mt][np * 2],     ah[mt], b0);                        \
                mma_f16(acc[mt][np * 2 + 1], ah[mt], b1);                        \
            }                                                                    \
        }                                                                        \
    }                                                                            \
} while (0)

    ISSUE(0, 0);
    ISSUE(1, 1);
    for (int c = 0; c < NC; ++c) {
        if (c + 2 < NC) {
            ISSUE(c + 2, (c + 2) % 3);
            asm volatile("cp.async.wait_group 2;" ::: "memory");
        } else if (c + 1 < NC) {
            asm volatile("cp.async.wait_group 1;" ::: "memory");
        } else {
            asm volatile("cp.async.wait_group 0;" ::: "memory");
        }
        __syncthreads();
        COMPUTE(c % 3);
        __syncthreads();
    }

    if (!fuse) {
        float* Cb = C + bz * sC;
        const int rbase = m0 + wm * 64 + (lane >> 2);
        const int cbase = n0 + wn * 64 + (lane & 3) * 2;
        #pragma unroll
        for (int mt = 0; mt < 4; mt++) {
            #pragma unroll
            for (int nt = 0; nt < 8; nt++) {
                int row = rbase + mt * 16;
                int col = cbase + nt * 8;
                float bx = bias[col], by = bias[col + 1];
                float2 v0 = make_float2(acc[mt][nt][0] + bx, acc[mt][nt][1] + by);
                float2 v1 = make_float2(acc[mt][nt][2] + bx, acc[mt][nt][3] + by);
                *(float2*)(Cb + (size_t)row * ldc + col)       = v0;
                *(float2*)(Cb + (size_t)(row + 8) * ldc + col) = v1;
            }
        }
    } else {
        const int gcol = n0 + wn * 64;
        const int lsub = (lane & 3) * 2;
        #pragma unroll
        for (int mt = 0; mt < 4; mt++) {
            #pragma unroll
            for (int hf = 0; hf < 2; hf++) {
                const int row = m0 + wm * 64 + (lane >> 2) + mt * 16 + hf * 8;
                float v[16];
                #pragma unroll
                for (int nt = 0; nt < 8; nt++) {
                    v[nt * 2]     = acc[mt][nt][hf * 2];
                    v[nt * 2 + 1] = acc[mt][nt][hf * 2 + 1];
                }
                if (gcol < 512) {
                    float m = v[0];
                    #pragma unroll
                    for (int i = 1; i < 16; i++) m = fmaxf(m, v[i]);
                    m = fmaxf(m, __shfl_xor_sync(0xffffffffu, m, 1));
                    m = fmaxf(m, __shfl_xor_sync(0xffffffffu, m, 2));
                    float s = 0.f;
                    #pragma unroll
                    for (int i = 0; i < 16; i++) { v[i] = __expf(v[i] - m); s += v[i]; }
                    s += __shfl_xor_sync(0xffffffffu, s, 1);
                    s += __shfl_xor_sync(0xffffffffu, s, 2);
                    const float sc = QSCALE / s;
                    #pragma unroll
                    for (int nt = 0; nt < 8; nt++) {
                        __half2 p = __floats2half2_rn(v[nt * 2] * sc, v[nt * 2 + 1] * sc);
                        *(__half2*)(qh + (size_t)row * HID + gcol + lsub + nt * 8) = p;
                    }
                } else {
                    __half* dst = (gcol < 1024) ? kh : vh;
                    const int cb2 = gcol - ((gcol < 1024) ? 512 : 1024);
                    #pragma unroll
                    for (int nt = 0; nt < 8; nt++) {
                        __half2 p = __floats2half2_rn(v[nt * 2], v[nt * 2 + 1]);
                        *(__half2*)(dst + (size_t)row * HID + cb2 + lsub + nt * 8) = p;
                    }
                }
            }
        }
    }
#undef ISSUE
#undef COMPUTE
}

// ---------------------------------------------------------------------------
// x fp32 -> fp16
// ---------------------------------------------------------------------------
__global__ void cvt_x_kernel(const float4* __restrict__ x, uint2* __restrict__ xh)
{
    size_t i = (size_t)blockIdx.x * 256 + threadIdx.x;
    float4 v = x[i];
    uint2 hv;
    __half2 p0 = __floats2half2_rn(v.x, v.y);
    __half2 p1 = __floats2half2_rn(v.z, v.w);
    hv.x = *(uint32_t*)&p0;
    hv.y = *(uint32_t*)&p1;
    xh[i] = hv;
}

// ---------------------------------------------------------------------------
// pack Wq|Wk|Wv [1024][512] -> W^T fp16 [1536][1024]
// ---------------------------------------------------------------------------
__global__ void pack_w_kernel(const float* __restrict__ Wq, const float* __restrict__ Wk,
                              const float* __restrict__ Wv, __half* __restrict__ wth)
{
    __shared__ float t[32][33];
    const float* W = (blockIdx.z == 0) ? Wq : (blockIdx.z == 1) ? Wk : Wv;
    int k = blockIdx.x * 32 + threadIdx.y;
    int c = blockIdx.y * 32 + threadIdx.x;
    t[threadIdx.y][threadIdx.x] = W[(size_t)k * 512 + c];
    __syncthreads();
    int n  = blockIdx.z * 512 + blockIdx.y * 32 + threadIdx.y;
    int kk = blockIdx.x * 32 + threadIdx.x;
    wth[(size_t)n * 1024 + kk] = __float2half_rn(t[threadIdx.x][threadIdx.y]);
}

// ---------------------------------------------------------------------------
// k stats phase 1 (single pass, no max shift): per-(b, chunk, c) sum(exp(k)).
// ---------------------------------------------------------------------------
__global__ void k_stats_part(const __half* __restrict__ kh, float* __restrict__ psum)
{
    const int b  = blockIdx.z;
    const int ch = blockIdx.y;
    const int c  = blockIdx.x * 128 + threadIdx.x;
    const __half* base = kh + (size_t)b * SEQ * HID + (size_t)ch * CHROWS * HID + c;

    float s = 0.f;
    #pragma unroll 8
    for (int n = 0; n < CHROWS; n++)
        s += __expf(__half2float(base[(size_t)n * HID]));

    psum[((size_t)b * NCH + ch) * HID + c] = s;
}

// ---------------------------------------------------------------------------
// k stats phase 2: combine chunk partials. grid (HID/128, BATCH), block 128.
// ---------------------------------------------------------------------------
__global__ void k_stats_final(const float* __restrict__ psum, float* __restrict__ ksi)
{
    const int b = blockIdx.y;
    const int c = blockIdx.x * 128 + threadIdx.x;
    float s = 0.f;
    #pragma unroll
    for (int ch = 0; ch < NCH; ch++)
        s += psum[((size_t)b * NCH + ch) * HID + c];
    ksi[b * HID + c] = 1.0f / s;
}

// ---------------------------------------------------------------------------
// partial context over 256-token chunks from fp16 k/v buffers [16384][512]
// softk = exp(k) * ksi  (no max shift). grid (CCH, HEADS, BATCH).
// ---------------------------------------------------------------------------
__global__ __launch_bounds__(256, 4)
void context_kernel(const __half* __restrict__ kh, const __half* __restrict__ vh,
                    const float* __restrict__ ksi, float* __restrict__ ctxp)
{
    int chunk = blockIdx.x, h = blockIdx.y, b = blockIdx.z;
    int tx = threadIdx.x, ty = threadIdx.y;
    int tid = ty * 16 + tx;

    __shared__ float Ks[32][64];
    __shared__ float Vs[32][64];
    __shared__ float si[64];

    if (tid < 64) si[tid] = ksi[b * HID + h * DH + tid];
    __syncthreads();

    const __half* kb = kh + (size_t)b * SEQ * HID + h * DH;
    const __half* vb = vh + (size_t)b * SEQ * HID + h * DH;
    int n0 = chunk * CCROWS;

    float acc[4][4];
    #pragma unroll
    for (int r = 0; r < 4; r++)
        #pragma unroll
        for (int c = 0; c < 4; c++) acc[r][c] = 0.f;

    for (int nn = 0; nn < CCROWS; nn += 32) {
        int ii = tid >> 3;
        int d0 = (tid & 7) * 8;
        size_t off = (size_t)(n0 + nn + ii) * HID + d0;
        uint4 kv4 = *(const uint4*)(kb + off);
        uint4 vv4 = *(const uint4*)(vb + off);
        const __half2* kp = (const __half2*)&kv4;
        const __half2* vp = (const __half2*)&vv4;
        #pragma unroll
        for (int u = 0; u < 4; u++) {
            float2 kf = __half22float2(kp[u]);
            float2 vf = __half22float2(vp[u]);
            Ks[ii][d0 + u * 2 + 0] = __expf(kf.x) * si[d0 + u * 2 + 0];
            Ks[ii][d0 + u * 2 + 1] = __expf(kf.y) * si[d0 + u * 2 + 1];
            Vs[ii][d0 + u * 2 + 0] = vf.x;
            Vs[ii][d0 + u * 2 + 1] = vf.y;
        }
        __syncthreads();

        #pragma unroll
        for (int i = 0; i < 32; i++) {
            float4 rav = *(float4*)(&Ks[i][ty * 4]);
            float4 rbv = *(float4*)(&Vs[i][tx * 4]);
            float ra[4] = {rav.x, rav.y, rav.z, rav.w};
            float rb[4] = {rbv.x, rbv.y, rbv.z, rbv.w};
            #pragma unroll
            for (int r = 0; r < 4; r++)
                #pragma unroll
                for (int c = 0; c < 4; c++)
                    acc[r][c] += ra[r] * rb[c];
        }
        __syncthreads();
    }

    float* dst = ctxp + ((((size_t)chunk * BATCH + b) * HEADS + h) * DH) * DH;
    #pragma unroll
    for (int r = 0; r < 4; r++)
        #pragma unroll
        for (int c = 0; c < 4; c++)
            dst[(ty * 4 + r) * DH + tx * 4 + c] = acc[r][c];
}

// ---------------------------------------------------------------------------
// W2^T[b][j][k] = sum_e ctx[b][h][d][e]*Wo[h*64+e][j]  (k = h*64+d), fp16 out
// ---------------------------------------------------------------------------
__global__ void w2t_kernel(const float* __restrict__ ctxp, const float* __restrict__ Wo,
                           __half* __restrict__ w2th)
{
    int jt = blockIdx.x, h = blockIdx.y, b = blockIdx.z;
    int tx = threadIdx.x, ty = threadIdx.y;
    int tid = ty * 16 + tx;

    __shared__ float Cs[64][65];   // [d][e]
    __shared__ float Ws[64][64];   // [e][j]

    for (int l = tid; l < 4096; l += 256) {
        size_t base = ((size_t)b * HEADS + h) * 4096 + l;
        float s = 0.f;
        #pragma unroll
        for (int ch = 0; ch < CCH; ch++)
            s += ctxp[base + (size_t)ch * (BATCH * HEADS * 4096)];
        Cs[l >> 6][l & 63] = s;
    }
    for (int l = tid; l < 4096; l += 256) {
        int e = l >> 6, jj = l & 63;
        Ws[e][jj] = Wo[(size_t)(h * DH + e) * QD + jt * 64 + jj];
    }
    __syncthreads();

    float acc[4][4];
    #pragma unroll
    for (int a = 0; a < 4; a++)
        #pragma unroll
        for (int d = 0; d < 4; d++) acc[a][d] = 0.f;

    #pragma unroll
    for (int e = 0; e < 64; e++) {
        float wv[4], cv[4];
        #pragma unroll
        for (int a = 0; a < 4; a++) wv[a] = Ws[e][ty * 4 + a];
        #pragma unroll
        for (int d = 0; d < 4; d++) cv[d] = Cs[tx * 4 + d][e];
        #pragma unroll
        for (int a = 0; a < 4; a++)
            #pragma unroll
            for (int d = 0; d < 4; d++)
                acc[a][d] += wv[a] * cv[d];
    }

    #pragma unroll
    for (int a = 0; a < 4; a++) {
        int j = jt * 64 + ty * 4 + a;
        #pragma unroll
        for (int d = 0; d < 4; d++) {
            int kc = h * DH + tx * 4 + d;
            w2th[((size_t)b * QD + j) * HID + kc] = __float2half_rn(acc[a][d]);
        }
    }
}

// ---------------------------------------------------------------------------
extern "C" void kernel_launch(void* const* d_in, const int* in_sizes, int n_in,
                              void* d_out, int out_size)
{
    const float* x  = (const float*)d_in[0];
    const float* Wq = (const float*)d_in[1];
    const float* Wk = (const float*)d_in[2];
    const float* Wv = (const float*)d_in[3];
    const float* Wo = (const float*)d_in[4];
    const float* bo = (const float*)d_in[5];
    float* out = (float*)d_out;

    unsigned char* sc = nullptr;
    cudaGetSymbolAddress((void**)&sc, g_scratch);

    __half*  xh   = (__half*) (sc + SC_XH);
    __half*  wth  = (__half*) (sc + SC_WTH);
    __half*  qh   = (__half*) (sc + SC_QH);
    __half*  kh   = (__half*) (sc + SC_KH);
    __half*  vh   = (__half*) (sc + SC_VH);
    float*   ksi  = (float*)  (sc + SC_KSI);
    float*   ctxp = (float*)  (sc + SC_CTXP);
    __half*  w2h  = (__half*) (sc + SC_W2TH);
    float*   psum = (float*)  (sc + SC_PSUM);

    cudaFuncSetAttribute(gemm_mma, cudaFuncAttributeMaxDynamicSharedMemorySize, GSM_TOTAL);

    // 1) conversions
    cvt_x_kernel<<<MROWS * QD / (256 * 4), 256>>>((const float4*)x, (uint2*)xh);
    pack_w_kernel<<<dim3(32, 16, 3), dim3(32, 32)>>>(Wq, Wk, Wv, wth);

    // 2) QKV fused GEMM + fused softmax/convert epilogue
    gemm_mma<<<dim3(NTOT / 256, MROWS / 128, 1), 256, GSM_TOTAL>>>(
        xh, wth, nullptr, nullptr, qh, kh, vh, 1, QD, 0, 0, 0, 0);

    // 3) k stats (single-pass exp-sum, chunked 2-phase)
    k_stats_part <<<dim3(HID / 128, NCH, BATCH), 128>>>(kh, psum);
    k_stats_final<<<dim3(HID / 128, BATCH), 128>>>(psum, ksi);

    // 4) partial context (16 chunks of 256 tokens)
    context_kernel<<<dim3(CCH, HEADS, BATCH), dim3(16, 16)>>>(kh, vh, ksi, ctxp);

    // 5) W2^T build (fp16)
    w2t_kernel<<<dim3(16, HEADS, BATCH), dim3(16, 16)>>>(ctxp, Wo, w2h);

    // 6) final batched GEMM: out[b] = q_soft[b] @ W2[b] + bo
    gemm_mma<<<dim3(QD / 256, SEQ / 128, BATCH), 256, GSM_TOTAL>>>(
        qh, w2h, out, bo, nullptr, nullptr, nullptr, 0, HID, QD,
        (long long)SEQ * HID, (long long)QD * HID, (long long)SEQ * QD);
}

// round 16
// speedup vs baseline: 1.4932x; 1.0001x over previous
#include <cuda_runtime.h>
#include <cuda_fp16.h>
#include <cstdint>

// ---------------- problem constants ----------------
#define BATCH 4
#define SEQ   4096
#define QD    1024
#define HEADS 8
#define DH    64
#define HID   512
#define MROWS (BATCH*SEQ)     // 16384
#define NTOT  1536            // q|k|v packed columns
#define QSCALE 0.125f
#define NCH   64              // n-chunks for k stats
#define CHROWS (SEQ/NCH)      // 64
#define CCH   16              // n-chunks for context
#define CCROWS (SEQ/CCH)      // 256

// ---------------- scratch layout (bytes) ----------------
#define SC_XH     0ull                   // x fp16 [16384][1024]
#define SC_WTH    33554432ull            // W^T fp16 [1536][1024]
#define SC_QH     36700160ull            // q_soft fp16 [16384][512]
#define SC_KH     53477376ull            // exp(k) fp16 [16384][512]
#define SC_VH     70254592ull            // v fp16 [16384][512]
#define SC_KSI    87031808ull            // [4][512] fp32
#define SC_CTXP   87040000ull            // [16][4][8][64][64] fp32 = 8388608 B
#define SC_W2TH   95428608ull            // W2^T fp16 [4][1024][512]
#define SC_PSUM   99622912ull            // [4][64][512] fp32
#define SC_TOTAL  100147200ull

__device__ __align__(1024) unsigned char g_scratch[SC_TOTAL];

// ---------------- PTX helpers ----------------
__device__ __forceinline__ uint32_t smem_u32(const void* p) {
    uint32_t a;
    asm("{ .reg .u64 t; cvta.to.shared.u64 t, %1; cvt.u32.u64 %0, t; }" : "=r"(a) : "l"(p));
    return a;
}
__device__ __forceinline__ void cp_async16(uint32_t dst, const void* src) {
    asm volatile("cp.async.cg.shared.global [%0], [%1], 16;" :: "r"(dst), "l"(src) : "memory");
}
__device__ __forceinline__ void cp_commit() {
    asm volatile("cp.async.commit_group;" ::: "memory");
}
__device__ __forceinline__ void ldsm_x4(uint32_t& r0, uint32_t& r1, uint32_t& r2, uint32_t& r3,
                                        uint32_t addr) {
    asm volatile("ldmatrix.sync.aligned.m8n8.x4.shared.b16 {%0,%1,%2,%3}, [%4];"
                 : "=r"(r0), "=r"(r1), "=r"(r2), "=r"(r3) : "r"(addr));
}
__device__ __forceinline__ void mma_f16(float* d, const uint32_t* a, const uint32_t* b) {
    asm volatile(
        "mma.sync.aligned.m16n8k16.row.col.f32.f16.f16.f32 "
        "{%0,%1,%2,%3}, {%4,%5,%6,%7}, {%8,%9}, {%0,%1,%2,%3};"
        : "+f"(d[0]), "+f"(d[1]), "+f"(d[2]), "+f"(d[3])
        : "r"(a[0]), "r"(a[1]), "r"(a[2]), "r"(a[3]), "r"(b[0]), "r"(b[1]));
}

// smem stage: A 16KB | B 32KB = 48KB per stage, 3 stages = 144KB
#define STG_B  16384
#define STG_SZ 49152
#define GSM_TOTAL (3*STG_SZ)   // 147456

// ---------------------------------------------------------------------------
// pure fp16 GEMM via mma.sync: C = A @ B^T.  (R10/R12 mainloop — frozen)
// CTA tile 128(M) x 256(N), BK=64, 256 threads (8 warps 2x4; warp = 64x64).
// fuse=0: fp32 out + bias. fuse=1: QKV epilogue — q softmax; k stored as
// exp(k) fp16 (in-place transform, no extra live state); v stored fp16.
// grid: (N/256, M/128, batch)
// ---------------------------------------------------------------------------
__global__ __launch_bounds__(256, 1)
void gemm_mma(const __half* __restrict__ A, const __half* __restrict__ B,
              float* __restrict__ C, const float* __restrict__ bias,
              __half* __restrict__ qh, __half* __restrict__ kh, __half* __restrict__ vh,
              int fuse, int K, int ldc,
              long long sA, long long sB, long long sC)
{
    extern __shared__ char smem[];
    const uint32_t sb = smem_u32(smem);
    const int tid  = threadIdx.x;
    const int wid  = tid >> 5;
    const int lane = tid & 31;
    const int wm = wid >> 2;           // 0..1
    const int wn = wid & 3;            // 0..3

    const int n0 = blockIdx.x * 256;
    const int m0 = blockIdx.y * 128;
    const long long bz = blockIdx.z;
    const __half* aP = A + bz * sA + (size_t)m0 * K;
    const __half* bP = B + bz * sB + (size_t)n0 * K;

    const int NC = K >> 6;

    float acc[4][8][4];
    #pragma unroll
    for (int i = 0; i < 4; i++)
        #pragma unroll
        for (int j = 0; j < 8; j++)
            #pragma unroll
            for (int l = 0; l < 4; l++) acc[i][j][l] = 0.f;

    const int g  = lane >> 3;     // ldmatrix address group 0..3
    const int lr = lane & 7;

#define ISSUE(cc, ss) do {                                                       \
    const int ck_ = (cc) << 6;                                                   \
    const uint32_t bs_ = sb + (ss) * STG_SZ;                                     \
    _Pragma("unroll")                                                            \
    for (int j_ = 0; j_ < 4; j_++) {                                             \
        int idx_ = tid + j_ * 256;                                               \
        int r_ = idx_ >> 3, c16_ = idx_ & 7;                                     \
        uint32_t d_ = bs_ + (uint32_t)(r_ * 128 + ((c16_ ^ (r_ & 7)) << 4));     \
        cp_async16(d_, aP + (size_t)r_ * K + ck_ + c16_ * 8);                    \
    }                                                                            \
    _Pragma("unroll")                                                            \
    for (int j_ = 0; j_ < 8; j_++) {                                             \
        int idx_ = tid + j_ * 256;                                               \
        int r_ = idx_ >> 3, c16_ = idx_ & 7;                                     \
        uint32_t d_ = bs_ + STG_B + (uint32_t)(r_ * 128 + ((c16_ ^ (r_ & 7)) << 4)); \
        cp_async16(d_, bP + (size_t)r_ * K + ck_ + c16_ * 8);                    \
    }                                                                            \
    cp_commit();                                                                 \
} while (0)

#define COMPUTE(ss) do {                                                         \
    const uint32_t bs_ = sb + (ss) * STG_SZ;                                     \
    _Pragma("unroll")                                                            \
    for (int ks = 0; ks < 4; ks++) {                                             \
        uint32_t ah[4][4];                                                       \
        _Pragma("unroll")                                                        \
        for (int mt = 0; mt < 4; mt++) {                                         \
            int r_ = wm * 64 + mt * 16 + lr + (g & 1) * 8;                       \
            int cA_ = ks * 2 + (g >> 1);                                         \
            uint32_t ad_ = bs_ + (uint32_t)(r_ * 128 + ((cA_ ^ (r_ & 7)) << 4)); \
            ldsm_x4(ah[mt][0], ah[mt][1], ah[mt][2], ah[mt][3], ad_);            \
        }                                                                        \
        _Pragma("unroll")                                                        \
        for (int np = 0; np < 4; np++) {                                         \
            int n_ = wn * 64 + np * 16 + lr + (g >> 1) * 8;                      \
            int cB_ = ks * 2 + (g & 1);                                          \
            uint32_t bd_ = bs_ + STG_B +                                         \
                           (uint32_t)(n_ * 128 + ((cB_ ^ (n_ & 7)) << 4));       \
            uint32_t b0[2], b1[2], t0, t1, t2, t3;                               \
            ldsm_x4(t0, t1, t2, t3, bd_);                                        \
            b0[0] = t0; b0[1] = t1; b1[0] = t2; b1[1] = t3;                      \
            _Pragma("unroll")                                                    \
            for (int mt = 0; mt < 4; mt++) {                                     \
                mma_f16(acc[mt][np * 2],     ah[mt], b0);                        \
                mma_f16(acc[mt][np * 2 + 1], ah[mt], b1);                        \
            }                                                                    \
        }                                                                        \
    }                                                                            \
} while (0)

    ISSUE(0, 0);
    ISSUE(1, 1);
    for (int c = 0; c < NC; ++c) {
        if (c + 2 < NC) {
            ISSUE(c + 2, (c + 2) % 3);
            asm volatile("cp.async.wait_group 2;" ::: "memory");
        } else if (c + 1 < NC) {
            asm volatile("cp.async.wait_group 1;" ::: "memory");
        } else {
            asm volatile("cp.async.wait_group 0;" ::: "memory");
        }
        __syncthreads();
        COMPUTE(c % 3);
        __syncthreads();
    }

    if (!fuse) {
        float* Cb = C + bz * sC;
        const int rbase = m0 + wm * 64 + (lane >> 2);
        const int cbase = n0 + wn * 64 + (lane & 3) * 2;
        #pragma unroll
        for (int mt = 0; mt < 4; mt++) {
            #pragma unroll
            for (int nt = 0; nt < 8; nt++) {
                int row = rbase + mt * 16;
                int col = cbase + nt * 8;
                float bx = bias[col], by = bias[col + 1];
                float2 v0 = make_float2(acc[mt][nt][0] + bx, acc[mt][nt][1] + by);
                float2 v1 = make_float2(acc[mt][nt][2] + bx, acc[mt][nt][3] + by);
                *(float2*)(Cb + (size_t)row * ldc + col)       = v0;
                *(float2*)(Cb + (size_t)(row + 8) * ldc + col) = v1;
            }
        }
    } else {
        const int gcol = n0 + wn * 64;
        const int lsub = (lane & 3) * 2;
        #pragma unroll
        for (int mt = 0; mt < 4; mt++) {
            #pragma unroll
            for (int hf = 0; hf < 2; hf++) {
                const int row = m0 + wm * 64 + (lane >> 2) + mt * 16 + hf * 8;
                float v[16];
                #pragma unroll
                for (int nt = 0; nt < 8; nt++) {
                    v[nt * 2]     = acc[mt][nt][hf * 2];
                    v[nt * 2 + 1] = acc[mt][nt][hf * 2 + 1];
                }
                if (gcol < 512) {
                    float m = v[0];
                    #pragma unroll
                    for (int i = 1; i < 16; i++) m = fmaxf(m, v[i]);
                    m = fmaxf(m, __shfl_xor_sync(0xffffffffu, m, 1));
                    m = fmaxf(m, __shfl_xor_sync(0xffffffffu, m, 2));
                    float s = 0.f;
                    #pragma unroll
                    for (int i = 0; i < 16; i++) { v[i] = __expf(v[i] - m); s += v[i]; }
                    s += __shfl_xor_sync(0xffffffffu, s, 1);
                    s += __shfl_xor_sync(0xffffffffu, s, 2);
                    const float sc = QSCALE / s;
                    #pragma unroll
                    for (int nt = 0; nt < 8; nt++) {
                        __half2 p = __floats2half2_rn(v[nt * 2] * sc, v[nt * 2 + 1] * sc);
                        *(__half2*)(qh + (size_t)row * HID + gcol + lsub + nt * 8) = p;
                    }
                } else if (gcol < 1024) {
                    // k region: store exp(k) fp16 (in-place transform)
                    const int cb2 = gcol - 512;
                    #pragma unroll
                    for (int i = 0; i < 16; i++) v[i] = __expf(v[i]);
                    #pragma unroll
                    for (int nt = 0; nt < 8; nt++) {
                        __half2 p = __floats2half2_rn(v[nt * 2], v[nt * 2 + 1]);
                        *(__half2*)(kh + (size_t)row * HID + cb2 + lsub + nt * 8) = p;
                    }
                } else {
                    const int cb2 = gcol - 1024;
                    #pragma unroll
                    for (int nt = 0; nt < 8; nt++) {
                        __half2 p = __floats2half2_rn(v[nt * 2], v[nt * 2 + 1]);
                        *(__half2*)(vh + (size_t)row * HID + cb2 + lsub + nt * 8) = p;
                    }
                }
            }
        }
    }
#undef ISSUE
#undef COMPUTE
}

// ---------------------------------------------------------------------------
// x fp32 -> fp16
// ---------------------------------------------------------------------------
__global__ void cvt_x_kernel(const float4* __restrict__ x, uint2* __restrict__ xh)
{
    size_t i = (size_t)blockIdx.x * 256 + threadIdx.x;
    float4 v = x[i];
    uint2 hv;
    __half2 p0 = __floats2half2_rn(v.x, v.y);
    __half2 p1 = __floats2half2_rn(v.z, v.w);
    hv.x = *(uint32_t*)&p0;
    hv.y = *(uint32_t*)&p1;
    xh[i] = hv;
}

// ---------------------------------------------------------------------------
// pack Wq|Wk|Wv [1024][512] -> W^T fp16 [1536][1024]
// ---------------------------------------------------------------------------
__global__ void pack_w_kernel(const float* __restrict__ Wq, const float* __restrict__ Wk,
                              const float* __restrict__ Wv, __half* __restrict__ wth)
{
    __shared__ float t[32][33];
    const float* W = (blockIdx.z == 0) ? Wq : (blockIdx.z == 1) ? Wk : Wv;
    int k = blockIdx.x * 32 + threadIdx.y;
    int c = blockIdx.y * 32 + threadIdx.x;
    t[threadIdx.y][threadIdx.x] = W[(size_t)k * 512 + c];
    __syncthreads();
    int n  = blockIdx.z * 512 + blockIdx.y * 32 + threadIdx.y;
    int kk = blockIdx.x * 32 + threadIdx.x;
    wth[(size_t)n * 1024 + kk] = __float2half_rn(t[threadIdx.x][threadIdx.y]);
}

// ---------------------------------------------------------------------------
// k stats phase 1: per-(b, chunk, c) sum of exp(k) (already exponentiated).
// grid (HID/128, NCH, BATCH), block 128.
// ---------------------------------------------------------------------------
__global__ void k_stats_part(const __half* __restrict__ kh, float* __restrict__ psum)
{
    const int b  = blockIdx.z;
    const int ch = blockIdx.y;
    const int c  = blockIdx.x * 128 + threadIdx.x;
    const __half* base = kh + (size_t)b * SEQ * HID + (size_t)ch * CHROWS * HID + c;

    float s = 0.f;
    #pragma unroll 8
    for (int n = 0; n < CHROWS; n++)
        s += __half2float(base[(size_t)n * HID]);

    psum[((size_t)b * NCH + ch) * HID + c] = s;
}

// ---------------------------------------------------------------------------
// k stats phase 2: combine chunk partials. grid (HID/128, BATCH), block 128.
// ---------------------------------------------------------------------------
__global__ void k_stats_final(const float* __restrict__ psum, float* __restrict__ ksi)
{
    const int b = blockIdx.y;
    const int c = blockIdx.x * 128 + threadIdx.x;
    float s = 0.f;
    #pragma unroll
    for (int ch = 0; ch < NCH; ch++)
        s += psum[((size_t)b * NCH + ch) * HID + c];
    ksi[b * HID + c] = 1.0f / s;
}

// ---------------------------------------------------------------------------
// partial context over 256-token chunks; kh holds exp(k) fp16 already.
// softk = expk * ksi. grid (CCH, HEADS, BATCH).
// ---------------------------------------------------------------------------
__global__ __launch_bounds__(256, 4)
void context_kernel(const __half* __restrict__ kh, const __half* __restrict__ vh,
                    const float* __restrict__ ksi, float* __restrict__ ctxp)
{
    int chunk = blockIdx.x, h = blockIdx.y, b = blockIdx.z;
    int tx = threadIdx.x, ty = threadIdx.y;
    int tid = ty * 16 + tx;

    __shared__ float Ks[32][64];
    __shared__ float Vs[32][64];
    __shared__ float si[64];

    if (tid < 64) si[tid] = ksi[b * HID + h * DH + tid];
    __syncthreads();

    const __half* kb = kh + (size_t)b * SEQ * HID + h * DH;
    const __half* vb = vh + (size_t)b * SEQ * HID + h * DH;
    int n0 = chunk * CCROWS;

    float acc[4][4];
    #pragma unroll
    for (int r = 0; r < 4; r++)
        #pragma unroll
        for (int c = 0; c < 4; c++) acc[r][c] = 0.f;

    for (int nn = 0; nn < CCROWS; nn += 32) {
        int ii = tid >> 3;
        int d0 = (tid & 7) * 8;
        size_t off = (size_t)(n0 + nn + ii) * HID + d0;
        uint4 kv4 = *(const uint4*)(kb + off);
        uint4 vv4 = *(const uint4*)(vb + off);
        const __half2* kp = (const __half2*)&kv4;
        const __half2* vp = (const __half2*)&vv4;
        #pragma unroll
        for (int u = 0; u < 4; u++) {
            float2 kf = __half22float2(kp[u]);
            float2 vf = __half22float2(vp[u]);
            Ks[ii][d0 + u * 2 + 0] = kf.x * si[d0 + u * 2 + 0];
            Ks[ii][d0 + u * 2 + 1] = kf.y * si[d0 + u * 2 + 1];
            Vs[ii][d0 + u * 2 + 0] = vf.x;
            Vs[ii][d0 + u * 2 + 1] = vf.y;
        }
        __syncthreads();

        #pragma unroll
        for (int i = 0; i < 32; i++) {
            float4 rav = *(float4*)(&Ks[i][ty * 4]);
            float4 rbv = *(float4*)(&Vs[i][tx * 4]);
            float ra[4] = {rav.x, rav.y, rav.z, rav.w};
            float rb[4] = {rbv.x, rbv.y, rbv.z, rbv.w};
            #pragma unroll
            for (int r = 0; r < 4; r++)
                #pragma unroll
                for (int c = 0; c < 4; c++)
                    acc[r][c] += ra[r] * rb[c];
        }
        __syncthreads();
    }

    float* dst = ctxp + ((((size_t)chunk * BATCH + b) * HEADS + h) * DH) * DH;
    #pragma unroll
    for (int r = 0; r < 4; r++)
        #pragma unroll
        for (int c = 0; c < 4; c++)
            dst[(ty * 4 + r) * DH + tx * 4 + c] = acc[r][c];
}

// ---------------------------------------------------------------------------
// W2^T[b][j][k] = sum_e ctx[b][h][d][e]*Wo[h*64+e][j]  (k = h*64+d), fp16 out
// ---------------------------------------------------------------------------
__global__ void w2t_kernel(const float* __restrict__ ctxp, const float* __restrict__ Wo,
                           __half* __restrict__ w2th)
{
    int jt = blockIdx.x, h = blockIdx.y, b = blockIdx.z;
    int tx = threadIdx.x, ty = threadIdx.y;
    int tid = ty * 16 + tx;

    __shared__ float Cs[64][65];   // [d][e]
    __shared__ float Ws[64][64];   // [e][j]

    for (int l = tid; l < 4096; l += 256) {
        size_t base = ((size_t)b * HEADS + h) * 4096 + l;
        float s = 0.f;
        #pragma unroll
        for (int ch = 0; ch < CCH; ch++)
            s += ctxp[base + (size_t)ch * (BATCH * HEADS * 4096)];
        Cs[l >> 6][l & 63] = s;
    }
    for (int l = tid; l < 4096; l += 256) {
        int e = l >> 6, jj = l & 63;
        Ws[e][jj] = Wo[(size_t)(h * DH + e) * QD + jt * 64 + jj];
    }
    __syncthreads();

    float acc[4][4];
    #pragma unroll
    for (int a = 0; a < 4; a++)
        #pragma unroll
        for (int d = 0; d < 4; d++) acc[a][d] = 0.f;

    #pragma unroll
    for (int e = 0; e < 64; e++) {
        float wv[4], cv[4];
        #pragma unroll
        for (int a = 0; a < 4; a++) wv[a] = Ws[e][ty * 4 + a];
        #pragma unroll
        for (int d = 0; d < 4; d++) cv[d] = Cs[tx * 4 + d][e];
        #pragma unroll
        for (int a = 0; a < 4; a++)
            #pragma unroll
            for (int d = 0; d < 4; d++)
                acc[a][d] += wv[a] * cv[d];
    }

    #pragma unroll
    for (int a = 0; a < 4; a++) {
        int j = jt * 64 + ty * 4 + a;
        #pragma unroll
        for (int d = 0; d < 4; d++) {
            int kc = h * DH + tx * 4 + d;
            w2th[((size_t)b * QD + j) * HID + kc] = __float2half_rn(acc[a][d]);
        }
    }
}

// ---------------------------------------------------------------------------
extern "C" void kernel_launch(void* const* d_in, const int* in_sizes, int n_in,
                              void* d_out, int out_size)
{
    const float* x  = (const float*)d_in[0];
    const float* Wq = (const float*)d_in[1];
    const float* Wk = (const float*)d_in[2];
    const float* Wv = (const float*)d_in[3];
    const float* Wo = (const float*)d_in[4];
    const float* bo = (const float*)d_in[5];
    float* out = (float*)d_out;

    unsigned char* sc = nullptr;
    cudaGetSymbolAddress((void**)&sc, g_scratch);

    __half*  xh   = (__half*) (sc + SC_XH);
    __half*  wth  = (__half*) (sc + SC_WTH);
    __half*  qh   = (__half*) (sc + SC_QH);
    __half*  kh   = (__half*) (sc + SC_KH);
    __half*  vh   = (__half*) (sc + SC_VH);
    float*   ksi  = (float*)  (sc + SC_KSI);
    float*   ctxp = (float*)  (sc + SC_CTXP);
    __half*  w2h  = (__half*) (sc + SC_W2TH);
    float*   psum = (float*)  (sc + SC_PSUM);

    cudaFuncSetAttribute(gemm_mma, cudaFuncAttributeMaxDynamicSharedMemorySize, GSM_TOTAL);

    // 1) conversions
    cvt_x_kernel<<<MROWS * QD / (256 * 4), 256>>>((const float4*)x, (uint2*)xh);
    pack_w_kernel<<<dim3(32, 16, 3), dim3(32, 32)>>>(Wq, Wk, Wv, wth);

    // 2) QKV fused GEMM + softmax / exp(k) / v convert epilogue
    gemm_mma<<<dim3(NTOT / 256, MROWS / 128, 1), 256, GSM_TOTAL>>>(
        xh, wth, nullptr, nullptr, qh, kh, vh, 1, QD, 0, 0, 0, 0);

    // 3) k stats (pure sums now; exp already applied)
    k_stats_part <<<dim3(HID / 128, NCH, BATCH), 128>>>(kh, psum);
    k_stats_final<<<dim3(HID / 128, BATCH), 128>>>(psum, ksi);

    // 4) partial context (16 chunks of 256 tokens)
    context_kernel<<<dim3(CCH, HEADS, BATCH), dim3(16, 16)>>>(kh, vh, ksi, ctxp);

    // 5) W2^T build (fp16)
    w2t_kernel<<<dim3(16, HEADS, BATCH), dim3(16, 16)>>>(ctxp, Wo, w2h);

    // 6) final batched GEMM: out[b] = q_soft[b] @ W2[b] + bo
    gemm_mma<<<dim3(QD / 256, SEQ / 128, BATCH), 256, GSM_TOTAL>>>(
        qh, w2h, out, bo, nullptr, nullptr, nullptr, 0, HID, QD,
        (long long)SEQ * HID, (long long)QD * HID, (long long)SEQ * QD);
}

// round 17
// speedup vs baseline: 1.5607x; 1.0452x over previous
#include <cuda_runtime.h>
#include <cuda_fp16.h>
#include <cstdint>

// ---------------- problem constants ----------------
#define BATCH 4
#define SEQ   4096
#define QD    1024
#define HEADS 8
#define DH    64
#define HID   512
#define MROWS (BATCH*SEQ)     // 16384
#define NTOT  1536            // q|k|v packed columns
#define QSCALE 0.125f
#define CCH   16              // n-chunks for context
#define CCROWS (SEQ/CCH)      // 256

// ---------------- scratch layout (bytes) ----------------
#define SC_XH     0ull                   // x fp16 [16384][1024]
#define SC_WTH    33554432ull            // W^T fp16 [1536][1024]
#define SC_QH     36700160ull            // q_soft fp16 [16384][512]
#define SC_KH     53477376ull            // exp(k) fp16 [16384][512]
#define SC_VH     70254592ull            // v fp16 [16384][512]
#define SC_CTXP   87040000ull            // [16][4][8][64][64] fp32 = 8388608 B
#define SC_W2TH   95428608ull            // W2^T fp16 [4][1024][512]
#define SC_CSUM   99622912ull            // [16][4][8][64] fp32 colsum = 131072 B
#define SC_TOTAL  100147200ull

__device__ __align__(1024) unsigned char g_scratch[SC_TOTAL];

// ---------------- PTX helpers ----------------
__device__ __forceinline__ uint32_t smem_u32(const void* p) {
    uint32_t a;
    asm("{ .reg .u64 t; cvta.to.shared.u64 t, %1; cvt.u32.u64 %0, t; }" : "=r"(a) : "l"(p));
    return a;
}
__device__ __forceinline__ void cp_async16(uint32_t dst, const void* src) {
    asm volatile("cp.async.cg.shared.global [%0], [%1], 16;" :: "r"(dst), "l"(src) : "memory");
}
__device__ __forceinline__ void cp_commit() {
    asm volatile("cp.async.commit_group;" ::: "memory");
}
__device__ __forceinline__ void ldsm_x4(uint32_t& r0, uint32_t& r1, uint32_t& r2, uint32_t& r3,
                                        uint32_t addr) {
    asm volatile("ldmatrix.sync.aligned.m8n8.x4.shared.b16 {%0,%1,%2,%3}, [%4];"
                 : "=r"(r0), "=r"(r1), "=r"(r2), "=r"(r3) : "r"(addr));
}
__device__ __forceinline__ void mma_f16(float* d, const uint32_t* a, const uint32_t* b) {
    asm volatile(
        "mma.sync.aligned.m16n8k16.row.col.f32.f16.f16.f32 "
        "{%0,%1,%2,%3}, {%4,%5,%6,%7}, {%8,%9}, {%0,%1,%2,%3};"
        : "+f"(d[0]), "+f"(d[1]), "+f"(d[2]), "+f"(d[3])
        : "r"(a[0]), "r"(a[1]), "r"(a[2]), "r"(a[3]), "r"(b[0]), "r"(b[1]));
}

// smem stage: A 16KB | B 32KB = 48KB per stage, 3 stages = 144KB
#define STG_B  16384
#define STG_SZ 49152
#define GSM_TOTAL (3*STG_SZ)   // 147456

// ---------------------------------------------------------------------------
// pure fp16 GEMM via mma.sync: C = A @ B^T.  (R10/R12 mainloop — frozen)
// CTA tile 128(M) x 256(N), BK=64, 256 threads (8 warps 2x4; warp = 64x64).
// fuse=0: fp32 out + bias. fuse=1: QKV epilogue — q softmax; k stored as
// exp(k) fp16; v stored fp16.
// grid: (N/256, M/128, batch)
// ---------------------------------------------------------------------------
__global__ __launch_bounds__(256, 1)
void gemm_mma(const __half* __restrict__ A, const __half* __restrict__ B,
              float* __restrict__ C, const float* __restrict__ bias,
              __half* __restrict__ qh, __half* __restrict__ kh, __half* __restrict__ vh,
              int fuse, int K, int ldc,
              long long sA, long long sB, long long sC)
{
    extern __shared__ char smem[];
    const uint32_t sb = smem_u32(smem);
    const int tid  = threadIdx.x;
    const int wid  = tid >> 5;
    const int lane = tid & 31;
    const int wm = wid >> 2;           // 0..1
    const int wn = wid & 3;            // 0..3

    const int n0 = blockIdx.x * 256;
    const int m0 = blockIdx.y * 128;
    const long long bz = blockIdx.z;
    const __half* aP = A + bz * sA + (size_t)m0 * K;
    const __half* bP = B + bz * sB + (size_t)n0 * K;

    const int NC = K >> 6;

    float acc[4][8][4];
    #pragma unroll
    for (int i = 0; i < 4; i++)
        #pragma unroll
        for (int j = 0; j < 8; j++)
            #pragma unroll
            for (int l = 0; l < 4; l++) acc[i][j][l] = 0.f;

    const int g  = lane >> 3;     // ldmatrix address group 0..3
    const int lr = lane & 7;

#define ISSUE(cc, ss) do {                                                       \
    const int ck_ = (cc) << 6;                                                   \
    const uint32_t bs_ = sb + (ss) * STG_SZ;                                     \
    _Pragma("unroll")                                                            \
    for (int j_ = 0; j_ < 4; j_++) {                                             \
        int idx_ = tid + j_ * 256;                                               \
        int r_ = idx_ >> 3, c16_ = idx_ & 7;                                     \
        uint32_t d_ = bs_ + (uint32_t)(r_ * 128 + ((c16_ ^ (r_ & 7)) << 4));     \
        cp_async16(d_, aP + (size_t)r_ * K + ck_ + c16_ * 8);                    \
    }                                                                            \
    _Pragma("unroll")                                                            \
    for (int j_ = 0; j_ < 8; j_++) {                                             \
        int idx_ = tid + j_ * 256;                                               \
        int r_ = idx_ >> 3, c16_ = idx_ & 7;                                     \
        uint32_t d_ = bs_ + STG_B + (uint32_t)(r_ * 128 + ((c16_ ^ (r_ & 7)) << 4)); \
        cp_async16(d_, bP + (size_t)r_ * K + ck_ + c16_ * 8);                    \
    }                                                                            \
    cp_commit();                                                                 \
} while (0)

#define COMPUTE(ss) do {                                                         \
    const uint32_t bs_ = sb + (ss) * STG_SZ;                                     \
    _Pragma("unroll")                                                            \
    for (int ks = 0; ks < 4; ks++) {                                             \
        uint32_t ah[4][4];                                                       \
        _Pragma("unroll")                                                        \
        for (int mt = 0; mt < 4; mt++) {                                         \
            int r_ = wm * 64 + mt * 16 + lr + (g & 1) * 8;                       \
            int cA_ = ks * 2 + (g >> 1);                                         \
            uint32_t ad_ = bs_ + (uint32_t)(r_ * 128 + ((cA_ ^ (r_ & 7)) << 4)); \
            ldsm_x4(ah[mt][0], ah[mt][1], ah[mt][2], ah[mt][3], ad_);            \
        }                                                                        \
        _Pragma("unroll")                                                        \
        for (int np = 0; np < 4; np++) {                                         \
            int n_ = wn * 64 + np * 16 + lr + (g >> 1) * 8;                      \
            int cB_ = ks * 2 + (g & 1);                                          \
            uint32_t bd_ = bs_ + STG_B +                                         \
                           (uint32_t)(n_ * 128 + ((cB_ ^ (n_ & 7)) << 4));       \
            uint32_t b0[2], b1[2], t0, t1, t2, t3;                               \
            ldsm_x4(t0, t1, t2, t3, bd_);                                        \
            b0[0] = t0; b0[1] = t1; b1[0] = t2; b1[1] = t3;                      \
            _Pragma("unroll")                                                    \
            for (int mt = 0; mt < 4; mt++) {                                     \
                mma_f16(acc[mt][np * 2],     ah[mt], b0);                        \
                mma_f16(acc[mt][np * 2 + 1], ah[mt], b1);                        \
            }                                                                    \
        }                                                                        \
    }                                                                            \
} while (0)

    ISSUE(0, 0);
    ISSUE(1, 1);
    for (int c = 0; c < NC; ++c) {
        if (c + 2 < NC) {
            ISSUE(c + 2, (c + 2) % 3);
            asm volatile("cp.async.wait_group 2;" ::: "memory");
        } else if (c + 1 < NC) {
            asm volatile("cp.async.wait_group 1;" ::: "memory");
        } else {
            asm volatile("cp.async.wait_group 0;" ::: "memory");
        }
        __syncthreads();
        COMPUTE(c % 3);
        __syncthreads();
    }

    if (!fuse) {
        float* Cb = C + bz * sC;
        const int rbase = m0 + wm * 64 + (lane >> 2);
        const int cbase = n0 + wn * 64 + (lane & 3) * 2;
        #pragma unroll
        for (int mt = 0; mt < 4; mt++) {
            #pragma unroll
            for (int nt = 0; nt < 8; nt++) {
                int row = rbase + mt * 16;
                int col = cbase + nt * 8;
                float bx = bias[col], by = bias[col + 1];
                float2 v0 = make_float2(acc[mt][nt][0] + bx, acc[mt][nt][1] + by);
                float2 v1 = make_float2(acc[mt][nt][2] + bx, acc[mt][nt][3] + by);
                *(float2*)(Cb + (size_t)row * ldc + col)       = v0;
                *(float2*)(Cb + (size_t)(row + 8) * ldc + col) = v1;
            }
        }
    } else {
        const int gcol = n0 + wn * 64;
        const int lsub = (lane & 3) * 2;
        #pragma unroll
        for (int mt = 0; mt < 4; mt++) {
            #pragma unroll
            for (int hf = 0; hf < 2; hf++) {
                const int row = m0 + wm * 64 + (lane >> 2) + mt * 16 + hf * 8;
                float v[16];
                #pragma unroll
                for (int nt = 0; nt < 8; nt++) {
                    v[nt * 2]     = acc[mt][nt][hf * 2];
                    v[nt * 2 + 1] = acc[mt][nt][hf * 2 + 1];
                }
                if (gcol < 512) {
                    float m = v[0];
                    #pragma unroll
                    for (int i = 1; i < 16; i++) m = fmaxf(m, v[i]);
                    m = fmaxf(m, __shfl_xor_sync(0xffffffffu, m, 1));
                    m = fmaxf(m, __shfl_xor_sync(0xffffffffu, m, 2));
                    float s = 0.f;
                    #pragma unroll
                    for (int i = 0; i < 16; i++) { v[i] = __expf(v[i] - m); s += v[i]; }
                    s += __shfl_xor_sync(0xffffffffu, s, 1);
                    s += __shfl_xor_sync(0xffffffffu, s, 2);
                    const float sc = QSCALE / s;
                    #pragma unroll
                    for (int nt = 0; nt < 8; nt++) {
                        __half2 p = __floats2half2_rn(v[nt * 2] * sc, v[nt * 2 + 1] * sc);
                        *(__half2*)(qh + (size_t)row * HID + gcol + lsub + nt * 8) = p;
                    }
                } else if (gcol < 1024) {
                    const int cb2 = gcol - 512;
                    #pragma unroll
                    for (int i = 0; i < 16; i++) v[i] = __expf(v[i]);
                    #pragma unroll
                    for (int nt = 0; nt < 8; nt++) {
                        __half2 p = __floats2half2_rn(v[nt * 2], v[nt * 2 + 1]);
                        *(__half2*)(kh + (size_t)row * HID + cb2 + lsub + nt * 8) = p;
                    }
                } else {
                    const int cb2 = gcol - 1024;
                    #pragma unroll
                    for (int nt = 0; nt < 8; nt++) {
                        __half2 p = __floats2half2_rn(v[nt * 2], v[nt * 2 + 1]);
                        *(__half2*)(vh + (size_t)row * HID + cb2 + lsub + nt * 8) = p;
                    }
                }
            }
        }
    }
#undef ISSUE
#undef COMPUTE
}

// ---------------------------------------------------------------------------
// x fp32 -> fp16
// ---------------------------------------------------------------------------
__global__ void cvt_x_kernel(const float4* __restrict__ x, uint2* __restrict__ xh)
{
    size_t i = (size_t)blockIdx.x * 256 + threadIdx.x;
    float4 v = x[i];
    uint2 hv;
    __half2 p0 = __floats2half2_rn(v.x, v.y);
    __half2 p1 = __floats2half2_rn(v.z, v.w);
    hv.x = *(uint32_t*)&p0;
    hv.y = *(uint32_t*)&p1;
    xh[i] = hv;
}

// ---------------------------------------------------------------------------
// pack Wq|Wk|Wv [1024][512] -> W^T fp16 [1536][1024]
// ---------------------------------------------------------------------------
__global__ void pack_w_kernel(const float* __restrict__ Wq, const float* __restrict__ Wk,
                              const float* __restrict__ Wv, __half* __restrict__ wth)
{
    __shared__ float t[32][33];
    const float* W = (blockIdx.z == 0) ? Wq : (blockIdx.z == 1) ? Wk : Wv;
    int k = blockIdx.x * 32 + threadIdx.y;
    int c = blockIdx.y * 32 + threadIdx.x;
    t[threadIdx.y][threadIdx.x] = W[(size_t)k * 512 + c];
    __syncthreads();
    int n  = blockIdx.z * 512 + blockIdx.y * 32 + threadIdx.y;
    int kk = blockIdx.x * 32 + threadIdx.x;
    wth[(size_t)n * 1024 + kk] = __float2half_rn(t[threadIdx.x][threadIdx.y]);
}

// ---------------------------------------------------------------------------
// raw context over 256-token chunks + per-chunk column sums of expk.
// ctxp_raw[ch][b][h][d][e] = sum_n expk[n,d]*v[n,e]
// csum[ch][b][h][d]        = sum_n expk[n,d]
// grid (CCH, HEADS, BATCH), block (16,16).
// ---------------------------------------------------------------------------
__global__ __launch_bounds__(256, 4)
void context_kernel(const __half* __restrict__ kh, const __half* __restrict__ vh,
                    float* __restrict__ ctxp, float* __restrict__ csum)
{
    int chunk = blockIdx.x, h = blockIdx.y, b = blockIdx.z;
    int tx = threadIdx.x, ty = threadIdx.y;
    int tid = ty * 16 + tx;

    __shared__ float Ks[32][64];
    __shared__ float Vs[32][64];

    const __half* kb = kh + (size_t)b * SEQ * HID + h * DH;
    const __half* vb = vh + (size_t)b * SEQ * HID + h * DH;
    int n0 = chunk * CCROWS;

    float acc[4][4];
    #pragma unroll
    for (int r = 0; r < 4; r++)
        #pragma unroll
        for (int c = 0; c < 4; c++) acc[r][c] = 0.f;

    float cs[8];
    #pragma unroll
    for (int j = 0; j < 8; j++) cs[j] = 0.f;

    const int ii = tid >> 3;
    const int d0 = (tid & 7) * 8;

    for (int nn = 0; nn < CCROWS; nn += 32) {
        size_t off = (size_t)(n0 + nn + ii) * HID + d0;
        uint4 kv4 = *(const uint4*)(kb + off);
        uint4 vv4 = *(const uint4*)(vb + off);
        const __half2* kp = (const __half2*)&kv4;
        const __half2* vp = (const __half2*)&vv4;
        #pragma unroll
        for (int u = 0; u < 4; u++) {
            float2 kf = __half22float2(kp[u]);
            float2 vf = __half22float2(vp[u]);
            Ks[ii][d0 + u * 2 + 0] = kf.x;
            Ks[ii][d0 + u * 2 + 1] = kf.y;
            cs[u * 2 + 0] += kf.x;
            cs[u * 2 + 1] += kf.y;
            Vs[ii][d0 + u * 2 + 0] = vf.x;
            Vs[ii][d0 + u * 2 + 1] = vf.y;
        }
        __syncthreads();

        #pragma unroll
        for (int i = 0; i < 32; i++) {
            float4 rav = *(float4*)(&Ks[i][ty * 4]);
            float4 rbv = *(float4*)(&Vs[i][tx * 4]);
            float ra[4] = {rav.x, rav.y, rav.z, rav.w};
            float rb[4] = {rbv.x, rbv.y, rbv.z, rbv.w};
            #pragma unroll
            for (int r = 0; r < 4; r++)
                #pragma unroll
                for (int c = 0; c < 4; c++)
                    acc[r][c] += ra[r] * rb[c];
        }
        __syncthreads();
    }

    // column-sum reduce: write per-thread partials into Ks, reduce 32 rows
    #pragma unroll
    for (int j = 0; j < 8; j++) Ks[ii][d0 + j] = cs[j];
    __syncthreads();
    if (tid < 64) {
        float s = 0.f;
        #pragma unroll 8
        for (int i = 0; i < 32; i++) s += Ks[i][tid];
        csum[(((size_t)chunk * BATCH + b) * HEADS + h) * DH + tid] = s;
    }

    float* dst = ctxp + ((((size_t)chunk * BATCH + b) * HEADS + h) * DH) * DH;
    #pragma unroll
    for (int r = 0; r < 4; r++)
        #pragma unroll
        for (int c = 0; c < 4; c++)
            dst[(ty * 4 + r) * DH + tx * 4 + c] = acc[r][c];
}

// ---------------------------------------------------------------------------
// W2^T[b][j][k] = sum_e (ksi[d] * ctx_raw[b][h][d][e]) * Wo[h*64+e][j]
// ksi[d] = 1 / sum_ch csum[ch][b][h][d].  fp16 out. grid (16, HEADS, BATCH).
// ---------------------------------------------------------------------------
__global__ void w2t_kernel(const float* __restrict__ ctxp, const float* __restrict__ csum,
                           const float* __restrict__ Wo, __half* __restrict__ w2th)
{
    int jt = blockIdx.x, h = blockIdx.y, b = blockIdx.z;
    int tx = threadIdx.x, ty = threadIdx.y;
    int tid = ty * 16 + tx;

    __shared__ float Cs[64][65];   // [d][e]
    __shared__ float Ws[64][64];   // [e][j]
    __shared__ float ksig[64];

    if (tid < 64) {
        float s = 0.f;
        #pragma unroll
        for (int ch = 0; ch < CCH; ch++)
            s += csum[(((size_t)ch * BATCH + b) * HEADS + h) * DH + tid];
        ksig[tid] = 1.0f / s;
    }

    for (int l = tid; l < 4096; l += 256) {
        size_t base = ((size_t)b * HEADS + h) * 4096 + l;
        float s = 0.f;
        #pragma unroll
        for (int ch = 0; ch < CCH; ch++)
            s += ctxp[base + (size_t)ch * (BATCH * HEADS * 4096)];
        Cs[l >> 6][l & 63] = s;
    }
    for (int l = tid; l < 4096; l += 256) {
        int e = l >> 6, jj = l & 63;
        Ws[e][jj] = Wo[(size_t)(h * DH + e) * QD + jt * 64 + jj];
    }
    __syncthreads();

    // scale Cs rows by ksi[d]
    for (int l = tid; l < 4096; l += 256)
        Cs[l >> 6][l & 63] *= ksig[l >> 6];
    __syncthreads();

    float acc[4][4];
    #pragma unroll
    for (int a = 0; a < 4; a++)
        #pragma unroll
        for (int d = 0; d < 4; d++) acc[a][d] = 0.f;

    #pragma unroll
    for (int e = 0; e < 64; e++) {
        float wv[4], cv[4];
        #pragma unroll
        for (int a = 0; a < 4; a++) wv[a] = Ws[e][ty * 4 + a];
        #pragma unroll
        for (int d = 0; d < 4; d++) cv[d] = Cs[tx * 4 + d][e];
        #pragma unroll
        for (int a = 0; a < 4; a++)
            #pragma unroll
            for (int d = 0; d < 4; d++)
                acc[a][d] += wv[a] * cv[d];
    }

    #pragma unroll
    for (int a = 0; a < 4; a++) {
        int j = jt * 64 + ty * 4 + a;
        #pragma unroll
        for (int d = 0; d < 4; d++) {
            int kc = h * DH + tx * 4 + d;
            w2th[((size_t)b * QD + j) * HID + kc] = __float2half_rn(acc[a][d]);
        }
    }
}

// ---------------------------------------------------------------------------
extern "C" void kernel_launch(void* const* d_in, const int* in_sizes, int n_in,
                              void* d_out, int out_size)
{
    const float* x  = (const float*)d_in[0];
    const float* Wq = (const float*)d_in[1];
    const float* Wk = (const float*)d_in[2];
    const float* Wv = (const float*)d_in[3];
    const float* Wo = (const float*)d_in[4];
    const float* bo = (const float*)d_in[5];
    float* out = (float*)d_out;

    unsigned char* sc = nullptr;
    cudaGetSymbolAddress((void**)&sc, g_scratch);

    __half*  xh   = (__half*) (sc + SC_XH);
    __half*  wth  = (__half*) (sc + SC_WTH);
    __half*  qh   = (__half*) (sc + SC_QH);
    __half*  kh   = (__half*) (sc + SC_KH);
    __half*  vh   = (__half*) (sc + SC_VH);
    float*   ctxp = (float*)  (sc + SC_CTXP);
    __half*  w2h  = (__half*) (sc + SC_W2TH);
    float*   csum = (float*)  (sc + SC_CSUM);

    cudaFuncSetAttribute(gemm_mma, cudaFuncAttributeMaxDynamicSharedMemorySize, GSM_TOTAL);

    // 1) conversions
    cvt_x_kernel<<<MROWS * QD / (256 * 4), 256>>>((const float4*)x, (uint2*)xh);
    pack_w_kernel<<<dim3(32, 16, 3), dim3(32, 32)>>>(Wq, Wk, Wv, wth);

    // 2) QKV fused GEMM + softmax / exp(k) / v convert epilogue
    gemm_mma<<<dim3(NTOT / 256, MROWS / 128, 1), 256, GSM_TOTAL>>>(
        xh, wth, nullptr, nullptr, qh, kh, vh, 1, QD, 0, 0, 0, 0);

    // 3) raw context + per-chunk column sums (k stats folded in)
    context_kernel<<<dim3(CCH, HEADS, BATCH), dim3(16, 16)>>>(kh, vh, ctxp, csum);

    // 4) W2^T build with ksi normalization folded in
    w2t_kernel<<<dim3(16, HEADS, BATCH), dim3(16, 16)>>>(ctxp, csum, Wo, w2h);

    // 5) final batched GEMM: out[b] = q_soft[b] @ W2[b] + bo
    gemm_mma<<<dim3(QD / 256, SEQ / 128, BATCH), 256, GSM_TOTAL>>>(
        qh, w2h, out, bo, nullptr, nullptr, nullptr, 0, HID, QD,
        (long long)SEQ * HID, (long long)QD * HID, (long long)SEQ * QD);
}